// round 9
// baseline (speedup 1.0000x reference)
#include <cuda_runtime.h>
#include <cstdint>

#define N_NODES 100000
#define N_EDGES 3200000
#define F 128
#define HQ 256
#define ADIM 10

// Scratch (static __device__ arrays: allocation-free per harness rules)
__device__ __align__(16) float g_xw[(size_t)N_NODES * F];   // relu(x@We+be)@Wg
__device__ __align__(16) float g_h2[(size_t)N_NODES * F];   // relu(gcn output)
__device__ float g_dinv[N_NODES];
__device__ int   g_cnt[N_NODES];
__device__ int   g_start[N_NODES + 1];
__device__ int   g_cursor[N_NODES];
__device__ int   g_src[N_EDGES];
__device__ int   g_is64;

// ---- packed f32x2 helpers (Blackwell FFMA2 path) ----
static __device__ __forceinline__ unsigned long long pack2(float lo, float hi) {
    unsigned long long r;
    asm("mov.b64 %0, {%1, %2};" : "=l"(r) : "f"(lo), "f"(hi));
    return r;
}
static __device__ __forceinline__ void fma2(unsigned long long& d,
                                            unsigned long long a,
                                            unsigned long long b) {
    asm("fma.rn.f32x2 %0, %1, %2, %0;" : "+l"(d) : "l"(a), "l"(b));
}
static __device__ __forceinline__ float2 unpack2(unsigned long long v) {
    float2 f;
    asm("mov.b64 {%0, %1}, %2;" : "=f"(f.x), "=f"(f.y) : "l"(v));
    return f;
}

static __device__ __forceinline__ int eidx(const void* ei, int is64, long long pos) {
    return is64 ? (int)((const long long*)ei)[pos] : ((const int*)ei)[pos];
}

// ---- pre: dtype detect (block 0, warp 0) + zero histogram counters ----
__global__ void k_pre(const int* __restrict__ ei) {
    if (blockIdx.x == 0 && threadIdx.x < 32) {
        int v = ei[2 * threadIdx.x + 1];
        unsigned m = __ballot_sync(0xffffffffu, v != 0);
        if (threadIdx.x == 0) g_is64 = (m == 0) ? 1 : 0;
    }
    int i = blockIdx.x * blockDim.x + threadIdx.x;
    int stride = gridDim.x * blockDim.x;
    for (; i < N_NODES; i += stride) g_cnt[i] = 0;
}

// ---- histogram of dst (doubles as in-degree count) ----
__global__ void k_hist(const void* __restrict__ ei) {
    int is64 = g_is64;
    int e = blockIdx.x * blockDim.x + threadIdx.x;
    if (e < N_EDGES) atomicAdd(&g_cnt[eidx(ei, is64, (long long)N_EDGES + e)], 1);
}

// ---- single-block exclusive scan of g_cnt -> g_start/g_cursor; dinv = rsqrt(cnt+1) ----
__global__ void __launch_bounds__(1024) k_scan() {
    __shared__ int wsum[32];
    const int t = threadIdx.x;
    const int lane = t & 31, wid = t >> 5;
    const int C = (N_NODES + 1023) / 1024;  // 98 elements per thread
    const int base = t * C;

    int s = 0;
    for (int i = 0; i < C; i++) {
        int idx = base + i;
        if (idx < N_NODES) s += g_cnt[idx];
    }
    int inc = s;
    #pragma unroll
    for (int o = 1; o < 32; o <<= 1) {
        int n = __shfl_up_sync(0xffffffffu, inc, o);
        if (lane >= o) inc += n;
    }
    if (lane == 31) wsum[wid] = inc;
    __syncthreads();
    if (wid == 0) {
        int v = wsum[lane];
        int winc = v;
        #pragma unroll
        for (int o = 1; o < 32; o <<= 1) {
            int n = __shfl_up_sync(0xffffffffu, winc, o);
            if (lane >= o) winc += n;
        }
        wsum[lane] = winc - v;  // exclusive
    }
    __syncthreads();

    int excl = inc - s + wsum[wid];
    for (int i = 0; i < C; i++) {
        int idx = base + i;
        if (idx < N_NODES) {
            int c = g_cnt[idx];
            g_start[idx] = excl;
            g_cursor[idx] = excl;
            g_dinv[idx] = rsqrtf((float)(c + 1));
            excl += c;
        }
    }
    if (t == 0) g_start[N_NODES] = N_EDGES;
}

// ---- permute edges into dst-grouped order ----
__global__ void k_permute(const void* __restrict__ ei) {
    int is64 = g_is64;
    int e = blockIdx.x * blockDim.x + threadIdx.x;
    if (e < N_EDGES) {
        int s = eidx(ei, is64, e);
        int d = eidx(ei, is64, (long long)N_EDGES + e);
        int pos = atomicAdd(&g_cursor[d], 1);
        g_src[pos] = s;
    }
}

// ==================== fused1: xw = relu(x@We + be) @ Wg ====================
#define XT_S 132

__global__ void __launch_bounds__(256, 1)
k_fused1(const float* __restrict__ x, const float* __restrict__ We,
         const float* __restrict__ be, const float* __restrict__ Wg) {
    extern __shared__ float smem[];
    float* sW  = smem;                    // 128*128
    float* sXT = smem + 16384;            // 128 * XT_S
    float* sHT = sXT + 128 * XT_S;        // 128 * XT_S
    float* sBe = sHT + 128 * XT_S;        // 128

    const int tid = threadIdx.x;
    const int base = blockIdx.x * 128;

    for (int idx = tid; idx < 16384; idx += 256) sW[idx] = We[idx];
    if (tid < 128) sBe[tid] = be[tid];
    for (int idx = tid; idx < 128 * F; idx += 256) {
        int r = idx >> 7, c = idx & 127;
        int node = base + r;
        sXT[c * XT_S + r] = (node < N_NODES) ? x[(size_t)node * F + c] : 0.f;
    }
    __syncthreads();

    const int tr = tid & 15, tc = tid >> 4;
    const int r0 = tr * 8, c0 = tc * 8;

    unsigned long long acc[8][4];
    #pragma unroll
    for (int ri = 0; ri < 8; ri++)
        #pragma unroll
        for (int cj = 0; cj < 4; cj++)
            acc[ri][cj] = pack2(sBe[c0 + 2 * cj], sBe[c0 + 2 * cj + 1]);

    #pragma unroll 4
    for (int k = 0; k < F; k++) {
        float4 a0 = *(const float4*)&sXT[k * XT_S + r0];
        float4 a1 = *(const float4*)&sXT[k * XT_S + r0 + 4];
        float4 w0 = *(const float4*)&sW[k * F + c0];
        float4 w1 = *(const float4*)&sW[k * F + c0 + 4];
        unsigned long long w[4] = { pack2(w0.x, w0.y), pack2(w0.z, w0.w),
                                    pack2(w1.x, w1.y), pack2(w1.z, w1.w) };
        float a[8] = {a0.x, a0.y, a0.z, a0.w, a1.x, a1.y, a1.z, a1.w};
        #pragma unroll
        for (int ri = 0; ri < 8; ri++) {
            unsigned long long av = pack2(a[ri], a[ri]);
            #pragma unroll
            for (int cj = 0; cj < 4; cj++) fma2(acc[ri][cj], av, w[cj]);
        }
    }

    #pragma unroll
    for (int cj = 0; cj < 4; cj++) {
        float2 v[8];
        #pragma unroll
        for (int ri = 0; ri < 8; ri++) v[ri] = unpack2(acc[ri][cj]);
        int c = c0 + 2 * cj;
        *(float4*)&sHT[c * XT_S + r0] =
            make_float4(fmaxf(v[0].x, 0.f), fmaxf(v[1].x, 0.f),
                        fmaxf(v[2].x, 0.f), fmaxf(v[3].x, 0.f));
        *(float4*)&sHT[c * XT_S + r0 + 4] =
            make_float4(fmaxf(v[4].x, 0.f), fmaxf(v[5].x, 0.f),
                        fmaxf(v[6].x, 0.f), fmaxf(v[7].x, 0.f));
        *(float4*)&sHT[(c + 1) * XT_S + r0] =
            make_float4(fmaxf(v[0].y, 0.f), fmaxf(v[1].y, 0.f),
                        fmaxf(v[2].y, 0.f), fmaxf(v[3].y, 0.f));
        *(float4*)&sHT[(c + 1) * XT_S + r0 + 4] =
            make_float4(fmaxf(v[4].y, 0.f), fmaxf(v[5].y, 0.f),
                        fmaxf(v[6].y, 0.f), fmaxf(v[7].y, 0.f));
    }
    __syncthreads();
    for (int idx = tid; idx < 16384; idx += 256) sW[idx] = Wg[idx];
    __syncthreads();

    #pragma unroll
    for (int ri = 0; ri < 8; ri++)
        #pragma unroll
        for (int cj = 0; cj < 4; cj++) acc[ri][cj] = 0ULL;

    #pragma unroll 4
    for (int k = 0; k < F; k++) {
        float4 a0 = *(const float4*)&sHT[k * XT_S + r0];
        float4 a1 = *(const float4*)&sHT[k * XT_S + r0 + 4];
        float4 w0 = *(const float4*)&sW[k * F + c0];
        float4 w1 = *(const float4*)&sW[k * F + c0 + 4];
        unsigned long long w[4] = { pack2(w0.x, w0.y), pack2(w0.z, w0.w),
                                    pack2(w1.x, w1.y), pack2(w1.z, w1.w) };
        float a[8] = {a0.x, a0.y, a0.z, a0.w, a1.x, a1.y, a1.z, a1.w};
        #pragma unroll
        for (int ri = 0; ri < 8; ri++) {
            unsigned long long av = pack2(a[ri], a[ri]);
            #pragma unroll
            for (int cj = 0; cj < 4; cj++) fma2(acc[ri][cj], av, w[cj]);
        }
    }

    #pragma unroll
    for (int ri = 0; ri < 8; ri++) {
        int node = base + r0 + ri;
        if (node < N_NODES) {
            float* dst = &g_xw[(size_t)node * F + c0];
            *(ulonglong2*)(dst)     = make_ulonglong2(acc[ri][0], acc[ri][1]);
            *(ulonglong2*)(dst + 4) = make_ulonglong2(acc[ri][2], acc[ri][3]);
        }
    }
}

// ==================== aggregate: warp-per-node segment sum ====================
// h2[d] = relu( dinv[d] * sum_j dinv[src_j]*xw[src_j] + dinv[d]^2 * xw[d] + bg )
// 8-deep unroll: 8 independent L1/L2 gathers in flight per warp.
__global__ void __launch_bounds__(256)
k_aggregate(const float* __restrict__ bg) {
    int warp = (blockIdx.x * blockDim.x + threadIdx.x) >> 5;
    int lane = threadIdx.x & 31;
    if (warp >= N_NODES) return;

    const float4* xw4 = reinterpret_cast<const float4*>(g_xw);
    int j0 = g_start[warp], j1 = g_start[warp + 1];

    float4 a0 = make_float4(0.f, 0.f, 0.f, 0.f);
    float4 a1 = a0, a2 = a0, a3 = a0;

    int j = j0;
    for (; j + 8 <= j1; j += 8) {
        int   si[8];
        float ci[8];
        #pragma unroll
        for (int u = 0; u < 8; u++) si[u] = __ldg(&g_src[j + u]);
        #pragma unroll
        for (int u = 0; u < 8; u++) ci[u] = __ldg(&g_dinv[si[u]]);
        float4 v[8];
        #pragma unroll
        for (int u = 0; u < 8; u++) v[u] = __ldg(&xw4[(size_t)si[u] * 32 + lane]);
        a0.x += v[0].x * ci[0]; a0.y += v[0].y * ci[0]; a0.z += v[0].z * ci[0]; a0.w += v[0].w * ci[0];
        a1.x += v[1].x * ci[1]; a1.y += v[1].y * ci[1]; a1.z += v[1].z * ci[1]; a1.w += v[1].w * ci[1];
        a2.x += v[2].x * ci[2]; a2.y += v[2].y * ci[2]; a2.z += v[2].z * ci[2]; a2.w += v[2].w * ci[2];
        a3.x += v[3].x * ci[3]; a3.y += v[3].y * ci[3]; a3.z += v[3].z * ci[3]; a3.w += v[3].w * ci[3];
        a0.x += v[4].x * ci[4]; a0.y += v[4].y * ci[4]; a0.z += v[4].z * ci[4]; a0.w += v[4].w * ci[4];
        a1.x += v[5].x * ci[5]; a1.y += v[5].y * ci[5]; a1.z += v[5].z * ci[5]; a1.w += v[5].w * ci[5];
        a2.x += v[6].x * ci[6]; a2.y += v[6].y * ci[6]; a2.z += v[6].z * ci[6]; a2.w += v[6].w * ci[6];
        a3.x += v[7].x * ci[7]; a3.y += v[7].y * ci[7]; a3.z += v[7].z * ci[7]; a3.w += v[7].w * ci[7];
    }
    for (; j < j1; j++) {
        int s = __ldg(&g_src[j]);
        float c = __ldg(&g_dinv[s]);
        float4 v = __ldg(&xw4[(size_t)s * 32 + lane]);
        a0.x += v.x * c; a0.y += v.y * c; a0.z += v.z * c; a0.w += v.w * c;
    }
    float4 acc = make_float4(a0.x + a1.x + a2.x + a3.x,
                             a0.y + a1.y + a2.y + a3.y,
                             a0.z + a1.z + a2.z + a3.z,
                             a0.w + a1.w + a2.w + a3.w);

    float dd = g_dinv[warp];
    float dd2 = dd * dd;
    float4 self = __ldg(&xw4[(size_t)warp * 32 + lane]);
    float4 bgv = *reinterpret_cast<const float4*>(&bg[lane * 4]);
    float4 h;
    h.x = fmaxf(dd * acc.x + dd2 * self.x + bgv.x, 0.f);
    h.y = fmaxf(dd * acc.y + dd2 * self.y + bgv.y, 0.f);
    h.z = fmaxf(dd * acc.z + dd2 * self.z + bgv.z, 0.f);
    h.w = fmaxf(dd * acc.w + dd2 * self.w + bgv.w, 0.f);
    reinterpret_cast<float4*>(g_h2)[(size_t)warp * 32 + lane] = h;
}

// ==================== fused2: out = relu(h2@W1+b1)@W2+b2 ====================
#define HT_S 68

__global__ void __launch_bounds__(256, 1)
k_fused2(const float* __restrict__ W1, const float* __restrict__ b1,
         const float* __restrict__ W2, const float* __restrict__ b2,
         float* __restrict__ out) {
    extern __shared__ float smem[];
    float* sW1  = smem;                   // 32768
    float* sHT  = sW1 + 32768;            // 128 * HT_S
    float* sW2  = sHT + 128 * HT_S;       // 2560
    float* sB1  = sW2 + 2560;             // 256
    float* sB2  = sB1 + 256;              // 16
    float* sOut = sB2 + 16;               // 8 * 640

    const int tid = threadIdx.x;
    const int base = blockIdx.x * 64;

    for (int idx = tid; idx < 32768; idx += 256) sW1[idx] = W1[idx];
    for (int idx = tid; idx < 2560; idx += 256) sW2[idx] = W2[idx];
    sB1[tid] = b1[tid];
    if (tid < ADIM) sB2[tid] = b2[tid];

    for (int idx = tid; idx < 64 * F; idx += 256) {
        int r = idx >> 7, c = idx & 127;
        int node = base + r;
        sHT[c * HT_S + r] = (node < N_NODES) ? g_h2[(size_t)node * F + c] : 0.f;
    }
    __syncthreads();

    const int tr = tid & 7, tc = tid >> 3;
    const int r0 = tr * 8, c0 = tc * 8;
    const int lane = tid & 31, wrp = tid >> 5;

    unsigned long long acc[8][4];
    #pragma unroll
    for (int ri = 0; ri < 8; ri++)
        #pragma unroll
        for (int cj = 0; cj < 4; cj++)
            acc[ri][cj] = pack2(sB1[c0 + 2 * cj], sB1[c0 + 2 * cj + 1]);

    #pragma unroll 4
    for (int k = 0; k < F; k++) {
        float4 a0 = *(const float4*)&sHT[k * HT_S + r0];
        float4 a1 = *(const float4*)&sHT[k * HT_S + r0 + 4];
        float4 w0 = *(const float4*)&sW1[k * HQ + c0];
        float4 w1 = *(const float4*)&sW1[k * HQ + c0 + 4];
        unsigned long long w[4] = { pack2(w0.x, w0.y), pack2(w0.z, w0.w),
                                    pack2(w1.x, w1.y), pack2(w1.z, w1.w) };
        float a[8] = {a0.x, a0.y, a0.z, a0.w, a1.x, a1.y, a1.z, a1.w};
        #pragma unroll
        for (int ri = 0; ri < 8; ri++) {
            unsigned long long av = pack2(a[ri], a[ri]);
            #pragma unroll
            for (int cj = 0; cj < 4; cj++) fma2(acc[ri][cj], av, w[cj]);
        }
    }

    #pragma unroll
    for (int ri = 0; ri < 8; ri++) {
        float p[ADIM];
        #pragma unroll
        for (int a = 0; a < ADIM; a++) p[a] = 0.f;
        #pragma unroll
        for (int cj = 0; cj < 4; cj++) {
            float2 q = unpack2(acc[ri][cj]);
            q.x = fmaxf(q.x, 0.f);
            q.y = fmaxf(q.y, 0.f);
            const float* wa = &sW2[(c0 + 2 * cj) * ADIM];
            #pragma unroll
            for (int a = 0; a < ADIM; a++)
                p[a] += q.x * wa[a] + q.y * wa[ADIM + a];
        }
        #pragma unroll
        for (int a = 0; a < ADIM; a++) {
            p[a] += __shfl_xor_sync(0xffffffffu, p[a], 8);
            p[a] += __shfl_xor_sync(0xffffffffu, p[a], 16);
        }
        if (lane < 8) {
            int row = r0 + ri;
            #pragma unroll
            for (int a = 0; a < ADIM; a++)
                sOut[wrp * 640 + row * ADIM + a] = p[a];
        }
    }
    __syncthreads();

    for (int idx = tid; idx < 64 * ADIM; idx += 256) {
        float v = 0.f;
        #pragma unroll
        for (int w = 0; w < 8; w++) v += sOut[w * 640 + idx];
        int row = idx / ADIM, a = idx - row * ADIM;
        int node = base + row;
        if (node < N_NODES) out[(size_t)node * ADIM + a] = v + sB2[a];
    }
}

extern "C" void kernel_launch(void* const* d_in, const int* in_sizes, int n_in,
                              void* d_out, int out_size) {
    const float* x  = (const float*)d_in[0];
    const void*  ei = d_in[1];
    const float* We = (const float*)d_in[2];
    const float* be = (const float*)d_in[3];
    const float* Wg = (const float*)d_in[4];
    const float* bg = (const float*)d_in[5];
    const float* W1 = (const float*)d_in[6];
    const float* b1 = (const float*)d_in[7];
    const float* W2 = (const float*)d_in[8];
    const float* b2 = (const float*)d_in[9];
    float* out = (float*)d_out;

    const size_t smemA = (size_t)(16384 + 2 * 128 * XT_S + 128) * sizeof(float);
    const size_t smemC = (size_t)(32768 + 128 * HT_S + 2560 + 256 + 16 + 5120) * sizeof(float);
    cudaFuncSetAttribute(k_fused1, cudaFuncAttributeMaxDynamicSharedMemorySize, (int)smemA);
    cudaFuncSetAttribute(k_fused2, cudaFuncAttributeMaxDynamicSharedMemorySize, (int)smemC);

    // launch order keeps k_aggregate as the 6th launch (ncu -s 5 -c 1 profiles it)
    k_pre<<<98, 1024>>>((const int*)ei);                         // 1
    k_fused1<<<(N_NODES + 127) / 128, 256, smemA>>>(x, We, be, Wg); // 2
    k_hist<<<(N_EDGES + 255) / 256, 256>>>(ei);                  // 3
    k_scan<<<1, 1024>>>();                                       // 4
    k_permute<<<(N_EDGES + 255) / 256, 256>>>(ei);               // 5
    k_aggregate<<<(N_NODES * 32 + 255) / 256, 256>>>(bg);        // 6 <- profiled
    k_fused2<<<(N_NODES + 63) / 64, 256, smemC>>>(W1, b1, W2, b2, out); // 7
}